// round 14
// baseline (speedup 1.0000x reference)
#include <cuda_runtime.h>
#include <cuda_fp16.h>
#include <cstdint>

#define NTOT 16384
#define KN   16
#define NP   15
#define CIN  64
#define COUT 128
#define KTOT (NP * CIN)        // 960

// ---------------- global scratch ----------------
__device__ __half g_B[COUT * KTOT];             // [cout][k], fp16 (= W^T)
__device__ __half g_F[(size_t)NTOT * CIN];      // features fp16
__device__ int    g_cnt;

typedef unsigned long long u64;
typedef unsigned int u32;

__device__ __forceinline__ u32 h2pk(float a, float b) {
    __half ha = __float2half_rn(a), hb = __float2half_rn(b);
    unsigned short ua = *reinterpret_cast<unsigned short*>(&ha);
    unsigned short ub = *reinterpret_cast<unsigned short*>(&hb);
    return (u32)ua | ((u32)ub << 16);
}
__device__ __forceinline__ u32 smem_u32(const void* p) {
    u32 a; asm("{ .reg .u64 t; cvta.to.shared.u64 t, %1; cvt.u32.u64 %0, t; }"
               : "=r"(a) : "l"(p));
    return a;
}
__device__ __forceinline__ void ldmx4(u32* r, u32 addr) {
    asm volatile("ldmatrix.sync.aligned.m8n8.x4.shared.b16 {%0,%1,%2,%3}, [%4];"
                 : "=r"(r[0]), "=r"(r[1]), "=r"(r[2]), "=r"(r[3]) : "r"(addr));
}
__device__ __forceinline__ void ldmx4t(u32* r, u32 addr) {
    asm volatile("ldmatrix.sync.aligned.m8n8.x4.trans.shared.b16 {%0,%1,%2,%3}, [%4];"
                 : "=r"(r[0]), "=r"(r[1]), "=r"(r[2]), "=r"(r[3]) : "r"(addr));
}
__device__ __forceinline__ void mma_f16(float* d, const u32* a, const u32* b) {
    asm volatile("mma.sync.aligned.m16n8k16.row.col.f32.f16.f16.f32 "
                 "{%0,%1,%2,%3}, {%4,%5,%6,%7}, {%8,%9}, {%0,%1,%2,%3};"
                 : "+f"(d[0]), "+f"(d[1]), "+f"(d[2]), "+f"(d[3])
                 : "r"(a[0]), "r"(a[1]), "r"(a[2]), "r"(a[3]),
                   "r"(b[0]), "r"(b[1]));
}
__device__ __forceinline__ void mbar_init(u32 mb, u32 cnt) {
    asm volatile("mbarrier.init.shared.b64 [%0], %1;" :: "r"(mb), "r"(cnt) : "memory");
}
__device__ __forceinline__ void mbar_expect(u32 mb, u32 tx) {
    asm volatile("mbarrier.arrive.expect_tx.shared.b64 _, [%0], %1;"
                 :: "r"(mb), "r"(tx) : "memory");
}
__device__ __forceinline__ void mbar_wait(u32 mb, u32 parity) {
    asm volatile("{\n\t.reg .pred P;\n\tWL_%=:\n\t"
                 "mbarrier.try_wait.parity.acquire.cta.shared::cta.b64 P, [%0], %1;\n\t"
                 "@!P bra WL_%=;\n\t}" :: "r"(mb), "r"(parity) : "memory");
}
__device__ __forceinline__ void bulk_cp(u32 dst, const void* src, u32 bytes, u32 mb) {
    asm volatile("cp.async.bulk.shared::cta.global.mbarrier::complete_tx::bytes "
                 "[%0], [%1], %2, [%3];"
                 :: "r"(dst), "l"(src), "r"(bytes), "r"(mb) : "memory");
}

// ====== fused kernel: grid 512, 256 threads, QB=32, 2 CTAs/SM ======
#define NT 256
#define QB 32
#define SB 16
#define OFF_A    0             // 15 chunks x (32 rows x 128B swizzled), stride 4112
#define ACH      4112
#define OFF_SH   61696         // f-tile (256 x 144) OR B double buffer (2 x 18432)
#define FSTR     144
#define BSTR     144
#define BBUF     18432
#define OFF_INFL 98560         // 16q x 256 halves = 8192
#define OFF_KP   106752
#define OFF_Q    106944
#define OFF_NIDX 107328        // 2048
#define OFF_MB   109376        // mbarG +0, mbarB0 +8, mbarB1 +16
#define SMEM_TOT 109568

#define NCHUNK 15

__global__ __launch_bounds__(NT, 2)
void kpconv_fused(const float* __restrict__ query,
                  const float* __restrict__ support,
                  const int*   __restrict__ nidx,
                  const float* __restrict__ feats,
                  const float* __restrict__ kp,
                  const float* __restrict__ W,
                  float* __restrict__ out)
{
    extern __shared__ char sm[];
    const u32 sb = smem_u32(sm);
    float* s_kp   = (float*)(sm + OFF_KP);
    float* s_q    = (float*)(sm + OFF_Q);
    int*   s_nidx = (int*)(sm + OFF_NIDX);

    const int tid = threadIdx.x;
    const int bid = blockIdx.x;
    const int m0  = bid * QB;

    // ---- step 0a: W -> g_B fp16, CTAs 0..119 ----
    if (bid < 120) {
        int idx4 = bid * NT + tid;
        int n  = idx4 / 240;
        int kq = idx4 - n * 240;
        int k  = kq * 4;
        int p  = k >> 6, cin = k & 63;
        const float* wp = W + p * CIN * COUT + cin * COUT + n;
        float w0 = __ldg(wp);
        float w1 = __ldg(wp + COUT);
        float w2 = __ldg(wp + 2 * COUT);
        float w3 = __ldg(wp + 3 * COUT);
        uint2 vh = make_uint2(h2pk(w0, w1), h2pk(w2, w3));
        *(uint2*)(g_B + (size_t)n * KTOT + k) = vh;
    }
    // ---- step 0b: feats -> g_F fp16, CTAs 0..255 (64 rows each) ----
    if (bid < 256) {
        const float* fsrc = feats + (size_t)bid * 64 * CIN;
        __half*      fdst = g_F   + (size_t)bid * 64 * CIN;
        #pragma unroll
        for (int t = 0; t < 4; t++) {
            int idx = tid + t * NT;           // 0..1023 uint4 groups
            uint4 v = __ldg((const uint4*)fsrc + idx);
            uint2 h = make_uint2(h2pk(__uint_as_float(v.x), __uint_as_float(v.y)),
                                 h2pk(__uint_as_float(v.z), __uint_as_float(v.w)));
            *(uint2*)(fdst + idx * 4) = h;
        }
        __threadfence();
        __syncthreads();
        if (tid == 0) atomicAdd(&g_cnt, 1);
    }

    // ---- mbarrier init + metadata ----
    if (tid == 0) {
        mbar_init(sb + OFF_MB, NT);        // gather: every thread arrives
        mbar_init(sb + OFF_MB + 8, 128);   // B buf 0
        mbar_init(sb + OFF_MB + 16, 128);  // B buf 1
    }
    for (int i = tid; i < QB * KN; i += NT) s_nidx[i] = nidx[m0 * KN + i];
    if (tid < NP * 3)  s_kp[tid] = kp[tid];
    if (tid < QB * 3)  s_q[tid]  = query[m0 * 3 + tid];

    // ---- wait for g_F / g_B (all 256 converters are wave-1 resident) ----
    if (tid == 0) { while (atomicAdd(&g_cnt, 0) < 256) { } }
    __syncthreads();
    __threadfence();

    const int wid  = tid >> 5;
    const int lane = tid & 31;

    // frag addressing constants
    const int aprow = (lane & 7) + ((lane >> 3) & 1) * 8;
    const u32 abh   = (u32)(((lane >> 4) & 1) * 16);
    const int mgrp  = lane >> 3;
    const int krow  = (mgrp & 1) * 8 + (lane & 7);
    const u32 cbyte0 = (u32)((mgrp >> 1) * 16);

    // =================== phase A: aggregation into resident s_A ===============
    #pragma unroll
    for (int sbch = 0; sbch < 2; sbch++) {
        __syncthreads();   // f-tile free (prev sub-batch consumed)

        // gather: ONE bulk copy per (q,k) row, 128B linear into stride-144 tile
        {
            int m = s_nidx[sbch * 256 + tid];
            asm volatile("mbarrier.arrive.expect_tx.shared.b64 _, [%0], %1;"
                         :: "r"(sb + OFF_MB), "r"(128u) : "memory");
            bulk_cp(sb + OFF_SH + (u32)tid * FSTR, g_F + (size_t)m * CIN, 128,
                    sb + OFF_MB);
        }

        // influences while gather is in flight
        {
            int qq = tid >> 4;
            int kk = tid & 15;
            int m  = s_nidx[sbch * 256 + tid];
            int qg = sbch * SB + qq;
            float rx = support[m * 3 + 0] - s_q[qg * 3 + 0];
            float ry = support[m * 3 + 1] - s_q[qg * 3 + 1];
            float rz = support[m * 3 + 2] - s_q[qg * 3 + 2];
            __half* ib = (__half*)(sm + OFF_INFL) + qq * 256 + kk;
            #pragma unroll
            for (int p = 0; p < NP; p++) {
                float dx = rx - s_kp[p * 3 + 0];
                float dy = ry - s_kp[p * 3 + 1];
                float dz = rz - s_kp[p * 3 + 2];
                float d  = sqrtf(fmaf(dx, dx, fmaf(dy, dy, dz * dz)));
                ib[p * 16] = __float2half_rn(fmaxf(1.0f - d, 0.0f));
            }
            ib[15 * 16] = __half(0.0f);
        }
        mbar_wait(sb + OFF_MB, sbch & 1);
        __syncthreads();   // infl visible to all warps

        // per-query mma aggregation: 2 queries per warp
        #pragma unroll
        for (int i = 0; i < 2; i++) {
            const int q  = wid * 2 + i;        // 0..15
            const int Lq = sbch * SB + q;      // 0..31 row in s_A chunks

            u32 a[4];
            ldmx4(a, sb + OFF_INFL + (u32)(q * 512 + aprow * 32) + abh);

            const u32 fbase = sb + OFF_SH + (u32)((q * 16 + krow) * FSTR);
            const int prow = lane >> 2;
            const int c4   = lane & 3;
            const u32 swzL = (u32)((Lq & 7) * 16);

            #pragma unroll
            for (int cc = 0; cc < 4; cc++) {
                u32 b[4];
                ldmx4t(b, fbase + (u32)(cc * 32) + cbyte0);   // additive, no XOR
                float acc[2][4];
                #pragma unroll
                for (int h = 0; h < 2; h++)
                    #pragma unroll
                    for (int e = 0; e < 4; e++) acc[h][e] = 0.0f;
                mma_f16(acc[0], a, &b[0]);
                mma_f16(acc[1], a, &b[2]);

                // stage into s_A chunks p=prow (lo) and p=prow+8 (hi, skip 15)
                #pragma unroll
                for (int h = 0; h < 2; h++) {
                    u32 lo = h2pk(acc[h][0], acc[h][1]);
                    u32 hi = h2pk(acc[h][2], acc[h][3]);
                    u32 x  = (u32)((2 * cc + h) * 16);
                    u32 off = (u32)(Lq * 128) + (x ^ swzL) + (u32)(c4 * 4);
                    *(u32*)(sm + OFF_A + prow * ACH + off) = lo;
                    if (prow != 7)
                        *(u32*)(sm + OFF_A + (prow + 8) * ACH + off) = hi;
                }
            }
        }
    }
    __syncthreads();   // s_A complete; f-tile dead -> B buffers may start

    // =================== phase B: GEMM out[32x128] = s_A @ B^T ================
    const int wm = wid >> 2;
    const int wn = wid & 3;

    const int a_row  = wm * 16 + aprow;
    const u32 a_mask = (u32)((a_row & 7) * 16);
    const int b_row  = wn * 32 + (lane & 7) + ((lane >> 4) & 1) * 8;
    const int b_bh   = ((lane >> 3) & 1) * 16;

    float acc[4][4];
    #pragma unroll
    for (int ni = 0; ni < 4; ni++)
        #pragma unroll
        for (int e = 0; e < 4; e++) acc[ni][e] = 0.0f;

    auto issueB = [&](int c) {
        if (tid < 128) {
            u32 mb = sb + OFF_MB + 8 + (u32)(c & 1) * 8;
            asm volatile("mbarrier.arrive.expect_tx.shared.b64 _, [%0], %1;"
                         :: "r"(mb), "r"(128u) : "memory");
            bulk_cp(sb + OFF_SH + (u32)(c & 1) * BBUF + (u32)tid * BSTR,
                    g_B + (size_t)tid * KTOT + c * 64, 128, mb);
        }
    };

    issueB(0);
    issueB(1);

    for (int c = 0; c < NCHUNK; c++) {
        mbar_wait(sb + OFF_MB + 8 + (u32)(c & 1) * 8, (c >> 1) & 1);

        const u32 aBase = sb + OFF_A + (u32)c * ACH + (u32)(a_row * 128);
        const u32 bBase = sb + OFF_SH + (u32)(c & 1) * BBUF + (u32)(b_row * BSTR);

        #pragma unroll
        for (int ks = 0; ks < 4; ks++) {
            const u32 aOff = ((u32)(ks * 32) + abh) ^ a_mask;
            const u32 bOff = (u32)(ks * 32 + b_bh);          // additive

            u32 b[8];
            #pragma unroll
            for (int nj = 0; nj < 2; nj++)
                ldmx4(&b[nj * 4], bBase + (u32)(nj * 16 * BSTR) + bOff);

            u32 a[4];
            ldmx4(a, aBase + aOff);
            #pragma unroll
            for (int ni = 0; ni < 4; ni++)
                mma_f16(acc[ni], a, &b[(ni >> 1) * 4 + (ni & 1) * 2]);
        }
        __syncthreads();                   // all warps done with buffer (c&1)
        if (c + 2 < NCHUNK) issueB(c + 2);
    }

    // ---- epilogue ----
    {
        int row = m0 + wm * 16 + (lane >> 2);
        #pragma unroll
        for (int ni = 0; ni < 4; ni++) {
            int col = wn * 32 + ni * 8 + (lane & 3) * 2;
            *(float2*)(out + (size_t)row * COUT + col) =
                make_float2(acc[ni][0], acc[ni][1]);
            *(float2*)(out + (size_t)(row + 8) * COUT + col) =
                make_float2(acc[ni][2], acc[ni][3]);
        }
    }
}

// ================= launch =================
extern "C" void kernel_launch(void* const* d_in, const int* in_sizes, int n_in,
                              void* d_out, int out_size) {
    const float* query   = (const float*)d_in[0];
    const float* support = (const float*)d_in[1];
    const int*   nidx    = (const int*)d_in[2];
    const float* feats   = (const float*)d_in[3];
    const float* W       = (const float*)d_in[4];
    const float* kp      = (const float*)d_in[5];
    float* out = (float*)d_out;

    cudaFuncSetAttribute(kpconv_fused,
                         cudaFuncAttributeMaxDynamicSharedMemorySize, SMEM_TOT);
    kpconv_fused<<<NTOT / QB, NT, SMEM_TOT>>>(
        query, support, nidx, feats, kp, W, out);
}

// round 15
// speedup vs baseline: 1.4510x; 1.4510x over previous
#include <cuda_runtime.h>
#include <cuda_fp16.h>
#include <cstdint>

#define NTOT 16384
#define KN   16
#define NP   15
#define CIN  64
#define COUT 128
#define KTOT (NP * CIN)        // 960

// ---------------- global scratch ----------------
__device__ __half g_B[COUT * KTOT];             // [cout][k], fp16 (= W^T)
__device__ __half g_F[(size_t)NTOT * CIN];      // features fp16
__device__ int    g_cnt;

typedef unsigned long long u64;
typedef unsigned int u32;

__device__ __forceinline__ u32 h2pk(float a, float b) {
    __half ha = __float2half_rn(a), hb = __float2half_rn(b);
    unsigned short ua = *reinterpret_cast<unsigned short*>(&ha);
    unsigned short ub = *reinterpret_cast<unsigned short*>(&hb);
    return (u32)ua | ((u32)ub << 16);
}
__device__ __forceinline__ u32 smem_u32(const void* p) {
    u32 a; asm("{ .reg .u64 t; cvta.to.shared.u64 t, %1; cvt.u32.u64 %0, t; }"
               : "=r"(a) : "l"(p));
    return a;
}
__device__ __forceinline__ void ldmx4(u32* r, u32 addr) {
    asm volatile("ldmatrix.sync.aligned.m8n8.x4.shared.b16 {%0,%1,%2,%3}, [%4];"
                 : "=r"(r[0]), "=r"(r[1]), "=r"(r[2]), "=r"(r[3]) : "r"(addr));
}
__device__ __forceinline__ void ldmx4t(u32* r, u32 addr) {
    asm volatile("ldmatrix.sync.aligned.m8n8.x4.trans.shared.b16 {%0,%1,%2,%3}, [%4];"
                 : "=r"(r[0]), "=r"(r[1]), "=r"(r[2]), "=r"(r[3]) : "r"(addr));
}
__device__ __forceinline__ void mma_f16(float* d, const u32* a, const u32* b) {
    asm volatile("mma.sync.aligned.m16n8k16.row.col.f32.f16.f16.f32 "
                 "{%0,%1,%2,%3}, {%4,%5,%6,%7}, {%8,%9}, {%0,%1,%2,%3};"
                 : "+f"(d[0]), "+f"(d[1]), "+f"(d[2]), "+f"(d[3])
                 : "r"(a[0]), "r"(a[1]), "r"(a[2]), "r"(a[3]),
                   "r"(b[0]), "r"(b[1]));
}
__device__ __forceinline__ void cpa16(u32 dst, const void* src) {
    asm volatile("cp.async.cg.shared.global [%0], [%1], 16;"
                 :: "r"(dst), "l"(src) : "memory");
}

// ====== fused kernel: grid 512, 256 threads, QB=32, 2 CTAs/SM ======
#define NT 256
#define QB 32
#define SB 16
#define OFF_A    0             // 15 chunks x (32 rows x 128B, XOR swizzle), stride 4112
#define ACH      4112
#define OFF_SH   61696         // f-tile (256x128B swz) OR B dbl buffer (2x16384)
#define OFF_INFL 94464         // 16q x 256 halves = 8192
#define OFF_KP   102656
#define OFF_Q    102848
#define OFF_NIDX 103232        // 2048
#define SMEM_TOT 105472

#define NCHUNK 15
#define BTILE  16384

__global__ __launch_bounds__(NT, 2)
void kpconv_fused(const float* __restrict__ query,
                  const float* __restrict__ support,
                  const int*   __restrict__ nidx,
                  const float* __restrict__ feats,
                  const float* __restrict__ kp,
                  const float* __restrict__ W,
                  float* __restrict__ out)
{
    extern __shared__ char sm[];
    const u32 sb = smem_u32(sm);
    float* s_kp   = (float*)(sm + OFF_KP);
    float* s_q    = (float*)(sm + OFF_Q);
    int*   s_nidx = (int*)(sm + OFF_NIDX);

    const int tid = threadIdx.x;
    const int bid = blockIdx.x;
    const int m0  = bid * QB;

    // ---- step 0a: W -> g_B fp16, CTAs 0..119 ----
    if (bid < 120) {
        int idx4 = bid * NT + tid;
        int n  = idx4 / 240;
        int kq = idx4 - n * 240;
        int k  = kq * 4;
        int p  = k >> 6, cin = k & 63;
        const float* wp = W + p * CIN * COUT + cin * COUT + n;
        float w0 = __ldg(wp);
        float w1 = __ldg(wp + COUT);
        float w2 = __ldg(wp + 2 * COUT);
        float w3 = __ldg(wp + 3 * COUT);
        uint2 vh = make_uint2(h2pk(w0, w1), h2pk(w2, w3));
        *(uint2*)(g_B + (size_t)n * KTOT + k) = vh;
    }
    // ---- step 0b: feats -> g_F fp16, CTAs 0..255 (64 rows each) ----
    if (bid < 256) {
        const float* fsrc = feats + (size_t)bid * 64 * CIN;
        __half*      fdst = g_F   + (size_t)bid * 64 * CIN;
        #pragma unroll
        for (int t = 0; t < 4; t++) {
            int idx = tid + t * NT;
            uint4 v = __ldg((const uint4*)fsrc + idx);
            uint2 h = make_uint2(h2pk(__uint_as_float(v.x), __uint_as_float(v.y)),
                                 h2pk(__uint_as_float(v.z), __uint_as_float(v.w)));
            *(uint2*)(fdst + idx * 4) = h;
        }
        __threadfence();
        __syncthreads();
        if (tid == 0) atomicAdd(&g_cnt, 1);
    }

    // ---- metadata ----
    for (int i = tid; i < QB * KN; i += NT) s_nidx[i] = nidx[m0 * KN + i];
    if (tid < NP * 3)  s_kp[tid] = kp[tid];
    if (tid < QB * 3)  s_q[tid]  = query[m0 * 3 + tid];

    // ---- wait for g_F / g_B (256 converters all wave-1 resident @2 CTAs/SM) --
    if (tid == 0) { while (atomicAdd(&g_cnt, 0) < 256) { } }
    __syncthreads();
    __threadfence();

    const int wid  = tid >> 5;
    const int lane = tid & 31;

    // frag addressing constants (verified R12)
    const int aprow = (lane & 7) + ((lane >> 3) & 1) * 8;
    const u32 abh   = (u32)(((lane >> 4) & 1) * 16);
    const int mgrp  = lane >> 3;
    const int krow  = (mgrp & 1) * 8 + (lane & 7);
    const u32 cbyte0 = (u32)((mgrp >> 1) * 16);

    // =================== phase A: aggregation into resident s_A ===============
    #pragma unroll
    for (int sbch = 0; sbch < 2; sbch++) {
        __syncthreads();   // f-tile free (prev sub-batch consumed)

        // gather fp16 rows -> swizzled f-tile via 16B cp.async (no STS half)
        #pragma unroll
        for (int i = 0; i < 8; i++) {
            int g   = tid + i * NT;           // 0..2047
            int row = g >> 3;                 // local (q,k) row 0..255
            int c16 = g & 7;
            int m   = s_nidx[sbch * 256 + row];
            u32 dst = sb + OFF_SH + (u32)(row * 128)
                    + (((u32)(c16 * 16)) ^ ((u32)(row & 7) * 16));
            cpa16(dst, g_F + (size_t)m * CIN + c16 * 8);
        }
        asm volatile("cp.async.commit_group;" ::: "memory");

        // influences while gather is in flight
        {
            int qq = tid >> 4;
            int kk = tid & 15;
            int m  = s_nidx[sbch * 256 + tid];
            int qg = sbch * SB + qq;
            float rx = support[m * 3 + 0] - s_q[qg * 3 + 0];
            float ry = support[m * 3 + 1] - s_q[qg * 3 + 1];
            float rz = support[m * 3 + 2] - s_q[qg * 3 + 2];
            __half* ib = (__half*)(sm + OFF_INFL) + qq * 256 + kk;
            #pragma unroll
            for (int p = 0; p < NP; p++) {
                float dx = rx - s_kp[p * 3 + 0];
                float dy = ry - s_kp[p * 3 + 1];
                float dz = rz - s_kp[p * 3 + 2];
                float d  = sqrtf(fmaf(dx, dx, fmaf(dy, dy, dz * dz)));
                ib[p * 16] = __float2half_rn(fmaxf(1.0f - d, 0.0f));
            }
            ib[15 * 16] = __half(0.0f);
        }
        asm volatile("cp.async.wait_group 0;" ::: "memory");
        __syncthreads();

        // per-query mma aggregation: 2 queries per warp -> stage into s_A
        #pragma unroll
        for (int i = 0; i < 2; i++) {
            const int q  = wid * 2 + i;        // 0..15
            const int Lq = sbch * SB + q;      // 0..31 row in s_A chunks

            u32 a[4];
            ldmx4(a, sb + OFF_INFL + (u32)(q * 512 + aprow * 32) + abh);

            const u32 fbase = sb + OFF_SH + (u32)((q * 16 + krow) * 128);
            const u32 fswz  = (u32)((krow & 7) * 16);
            const int prow = lane >> 2;
            const int c4   = lane & 3;
            const u32 swzL = (u32)((Lq & 7) * 16);

            #pragma unroll
            for (int cc = 0; cc < 4; cc++) {
                u32 b[4];
                ldmx4t(b, fbase + (((u32)(cc * 32) + cbyte0) ^ fswz));
                float acc[2][4];
                #pragma unroll
                for (int h = 0; h < 2; h++)
                    #pragma unroll
                    for (int e = 0; e < 4; e++) acc[h][e] = 0.0f;
                mma_f16(acc[0], a, &b[0]);
                mma_f16(acc[1], a, &b[2]);

                // stage into s_A chunks p=prow (lo) and p=prow+8 (hi, skip p=15)
                #pragma unroll
                for (int h = 0; h < 2; h++) {
                    u32 lo = h2pk(acc[h][0], acc[h][1]);
                    u32 hi = h2pk(acc[h][2], acc[h][3]);
                    u32 x  = (u32)((2 * cc + h) * 16);
                    u32 off = (u32)(Lq * 128) + (x ^ swzL) + (u32)(c4 * 4);
                    *(u32*)(sm + OFF_A + prow * ACH + off) = lo;
                    if (prow != 7)
                        *(u32*)(sm + OFF_A + (prow + 8) * ACH + off) = hi;
                }
            }
        }
    }
    __syncthreads();   // s_A complete; f-tile dead -> B buffers may start

    // =================== phase B: GEMM out[32x128] = s_A @ B^T ================
    const int wm = wid >> 2;        // 0..1 (M groups of 16)
    const int wn = wid & 3;         // 0..3 (N groups of 32)

    const int a_row  = wm * 16 + aprow;
    const u32 a_mask = (u32)((a_row & 7) * 16);
    const int b_row  = wn * 32 + (lane & 7) + ((lane >> 4) & 1) * 8;
    const int b_bh   = ((lane >> 3) & 1) * 16;
    const u32 b_mask = (u32)((b_row & 7) * 16);

    float acc[4][4];
    #pragma unroll
    for (int ni = 0; ni < 4; ni++)
        #pragma unroll
        for (int e = 0; e < 4; e++) acc[ni][e] = 0.0f;

    auto issueB = [&](int c) {
        u32 dstb = sb + OFF_SH + (u32)(c & 1) * BTILE;
        #pragma unroll
        for (int j = 0; j < 4; j++) {
            int idx = tid + j * NT;               // 0..1023
            int row = idx >> 3, c16 = idx & 7;
            u32 dst = dstb + (u32)(row * 128 + ((c16 * 16) ^ ((row & 7) * 16)));
            cpa16(dst, g_B + (size_t)row * KTOT + c * 64 + c16 * 8);
        }
        asm volatile("cp.async.commit_group;" ::: "memory");
    };

    issueB(0);

    for (int c = 0; c < NCHUNK; c++) {
        if (c + 1 < NCHUNK) {
            issueB(c + 1);
            asm volatile("cp.async.wait_group 1;" ::: "memory");
        } else {
            asm volatile("cp.async.wait_group 0;" ::: "memory");
        }
        __syncthreads();

        const u32 aBase = sb + OFF_A + (u32)c * ACH + (u32)(a_row * 128);
        const u32 bBase = sb + OFF_SH + (u32)(c & 1) * BTILE + (u32)(b_row * 128);

        #pragma unroll
        for (int ks = 0; ks < 4; ks++) {
            const u32 aOff = ((u32)(ks * 32) + abh) ^ a_mask;
            const u32 bOff = (u32)((ks * 32 + b_bh)) ^ b_mask;

            u32 b[8];
            #pragma unroll
            for (int nj = 0; nj < 2; nj++)
                ldmx4(&b[nj * 4], bBase + (u32)(nj * 16 * 128) + bOff);

            u32 a[4];
            ldmx4(a, aBase + aOff);
            #pragma unroll
            for (int ni = 0; ni < 4; ni++)
                mma_f16(acc[ni], a, &b[(ni >> 1) * 4 + (ni & 1) * 2]);
        }
        __syncthreads();
    }

    // ---- epilogue ----
    {
        int row = m0 + wm * 16 + (lane >> 2);
        #pragma unroll
        for (int ni = 0; ni < 4; ni++) {
            int col = wn * 32 + ni * 8 + (lane & 3) * 2;
            *(float2*)(out + (size_t)row * COUT + col) =
                make_float2(acc[ni][0], acc[ni][1]);
            *(float2*)(out + (size_t)(row + 8) * COUT + col) =
                make_float2(acc[ni][2], acc[ni][3]);
        }
    }
}

// ================= launch =================
extern "C" void kernel_launch(void* const* d_in, const int* in_sizes, int n_in,
                              void* d_out, int out_size) {
    const float* query   = (const float*)d_in[0];
    const float* support = (const float*)d_in[1];
    const int*   nidx    = (const int*)d_in[2];
    const float* feats   = (const float*)d_in[3];
    const float* W       = (const float*)d_in[4];
    const float* kp      = (const float*)d_in[5];
    float* out = (float*)d_out;

    cudaFuncSetAttribute(kpconv_fused,
                         cudaFuncAttributeMaxDynamicSharedMemorySize, SMEM_TOT);
    kpconv_fused<<<NTOT / QB, NT, SMEM_TOT>>>(
        query, support, nidx, feats, kp, W, out);
}

// round 16
// speedup vs baseline: 1.5165x; 1.0452x over previous
#include <cuda_runtime.h>
#include <cuda_fp16.h>
#include <cstdint>

#define NTOT 16384
#define KN   16
#define NP   15
#define CIN  64
#define COUT 128
#define KTOT (NP * CIN)        // 960

// ---------------- global scratch ----------------
__device__ __half g_B[COUT * KTOT];             // [cout][k], fp16 (= W^T)
__device__ __half g_F[(size_t)NTOT * CIN];      // features fp16
__device__ int    g_cnt;

typedef unsigned long long u64;
typedef unsigned int u32;

__device__ __forceinline__ u32 h2pk(float a, float b) {
    __half ha = __float2half_rn(a), hb = __float2half_rn(b);
    unsigned short ua = *reinterpret_cast<unsigned short*>(&ha);
    unsigned short ub = *reinterpret_cast<unsigned short*>(&hb);
    return (u32)ua | ((u32)ub << 16);
}
__device__ __forceinline__ u32 smem_u32(const void* p) {
    u32 a; asm("{ .reg .u64 t; cvta.to.shared.u64 t, %1; cvt.u32.u64 %0, t; }"
               : "=r"(a) : "l"(p));
    return a;
}
__device__ __forceinline__ void ldmx4(u32* r, u32 addr) {
    asm volatile("ldmatrix.sync.aligned.m8n8.x4.shared.b16 {%0,%1,%2,%3}, [%4];"
                 : "=r"(r[0]), "=r"(r[1]), "=r"(r[2]), "=r"(r[3]) : "r"(addr));
}
__device__ __forceinline__ void ldmx4t(u32* r, u32 addr) {
    asm volatile("ldmatrix.sync.aligned.m8n8.x4.trans.shared.b16 {%0,%1,%2,%3}, [%4];"
                 : "=r"(r[0]), "=r"(r[1]), "=r"(r[2]), "=r"(r[3]) : "r"(addr));
}
__device__ __forceinline__ void mma_f16(float* d, const u32* a, const u32* b) {
    asm volatile("mma.sync.aligned.m16n8k16.row.col.f32.f16.f16.f32 "
                 "{%0,%1,%2,%3}, {%4,%5,%6,%7}, {%8,%9}, {%0,%1,%2,%3};"
                 : "+f"(d[0]), "+f"(d[1]), "+f"(d[2]), "+f"(d[3])
                 : "r"(a[0]), "r"(a[1]), "r"(a[2]), "r"(a[3]),
                   "r"(b[0]), "r"(b[1]));
}
__device__ __forceinline__ void cpa16(u32 dst, const void* src) {
    asm volatile("cp.async.cg.shared.global [%0], [%1], 16;"
                 :: "r"(dst), "l"(src) : "memory");
}

// ====== fused kernel: grid 512, 256 threads, QB=32, 2 CTAs/SM ======
#define NT 256
#define QB 32
#define SB 16
#define OFF_A    0             // 15 chunks x (32 rows x 128B, XOR swz), stride 4112
#define ACH      4112
#define OFF_SH   61696         // phase A: f-tile 32KB + infl 8KB | phase B: ring 3x16KB
#define OFF_INFL (OFF_SH + 32768)
#define OFF_KP   110848
#define OFF_Q    111040
#define OFF_NIDX 111424        // 2048 -> 113472
#define SMEM_TOT 113664

#define NCHUNK 15
#define BTILE  16384

__global__ __launch_bounds__(NT, 2)
void kpconv_fused(const float* __restrict__ query,
                  const float* __restrict__ support,
                  const int*   __restrict__ nidx,
                  const float* __restrict__ feats,
                  const float* __restrict__ kp,
                  const float* __restrict__ W,
                  float* __restrict__ out)
{
    extern __shared__ char sm[];
    const u32 sb = smem_u32(sm);
    float* s_kp   = (float*)(sm + OFF_KP);
    float* s_q    = (float*)(sm + OFF_Q);
    int*   s_nidx = (int*)(sm + OFF_NIDX);

    const int tid = threadIdx.x;
    const int bid = blockIdx.x;
    const int m0  = bid * QB;

    // ---- step 0a: W -> g_B fp16, CTAs 0..119 ----
    if (bid < 120) {
        int idx4 = bid * NT + tid;
        int n  = idx4 / 240;
        int kq = idx4 - n * 240;
        int k  = kq * 4;
        int p  = k >> 6, cin = k & 63;
        const float* wp = W + p * CIN * COUT + cin * COUT + n;
        float w0 = __ldg(wp);
        float w1 = __ldg(wp + COUT);
        float w2 = __ldg(wp + 2 * COUT);
        float w3 = __ldg(wp + 3 * COUT);
        uint2 vh = make_uint2(h2pk(w0, w1), h2pk(w2, w3));
        *(uint2*)(g_B + (size_t)n * KTOT + k) = vh;
    }
    // ---- step 0b: feats -> g_F fp16, CTAs 0..255 (64 rows each) ----
    if (bid < 256) {
        const float* fsrc = feats + (size_t)bid * 64 * CIN;
        __half*      fdst = g_F   + (size_t)bid * 64 * CIN;
        #pragma unroll
        for (int t = 0; t < 4; t++) {
            int idx = tid + t * NT;
            uint4 v = __ldg((const uint4*)fsrc + idx);
            uint2 h = make_uint2(h2pk(__uint_as_float(v.x), __uint_as_float(v.y)),
                                 h2pk(__uint_as_float(v.z), __uint_as_float(v.w)));
            *(uint2*)(fdst + idx * 4) = h;
        }
        __threadfence();
        __syncthreads();
        if (tid == 0) atomicAdd(&g_cnt, 1);
    }

    // ---- metadata ----
    for (int i = tid; i < QB * KN; i += NT) s_nidx[i] = nidx[m0 * KN + i];
    if (tid < NP * 3)  s_kp[tid] = kp[tid];
    if (tid < QB * 3)  s_q[tid]  = query[m0 * 3 + tid];

    // ---- wait for g_F / g_B via acquire loads (no atomic contention) ----
    if (tid == 0) {
        int v;
        do {
            asm volatile("ld.global.acquire.gpu.b32 %0, [%1];"
                         : "=r"(v) : "l"(&g_cnt) : "memory");
        } while (v < 256);
    }
    __syncthreads();
    __threadfence();

    const int wid  = tid >> 5;
    const int lane = tid & 31;

    // frag addressing constants (verified)
    const int aprow = (lane & 7) + ((lane >> 3) & 1) * 8;
    const u32 abh   = (u32)(((lane >> 4) & 1) * 16);
    const int mgrp  = lane >> 3;
    const int krow  = (mgrp & 1) * 8 + (lane & 7);
    const u32 cbyte0 = (u32)((mgrp >> 1) * 16);

    // =================== phase A: aggregation into resident s_A ===============
    #pragma unroll
    for (int sbch = 0; sbch < 2; sbch++) {
        __syncthreads();   // f-tile free (prev sub-batch consumed)

        // gather fp16 rows -> swizzled f-tile via 16B cp.async
        #pragma unroll
        for (int i = 0; i < 8; i++) {
            int g   = tid + i * NT;           // 0..2047
            int row = g >> 3;                 // local (q,k) row 0..255
            int c16 = g & 7;
            int m   = s_nidx[sbch * 256 + row];
            u32 dst = sb + OFF_SH + (u32)(row * 128)
                    + (((u32)(c16 * 16)) ^ ((u32)(row & 7) * 16));
            cpa16(dst, g_F + (size_t)m * CIN + c16 * 8);
        }
        asm volatile("cp.async.commit_group;" ::: "memory");

        // influences while gather is in flight
        {
            int qq = tid >> 4;
            int kk = tid & 15;
            int m  = s_nidx[sbch * 256 + tid];
            int qg = sbch * SB + qq;
            float rx = support[m * 3 + 0] - s_q[qg * 3 + 0];
            float ry = support[m * 3 + 1] - s_q[qg * 3 + 1];
            float rz = support[m * 3 + 2] - s_q[qg * 3 + 2];
            __half* ib = (__half*)(sm + OFF_INFL) + qq * 256 + kk;
            #pragma unroll
            for (int p = 0; p < NP; p++) {
                float dx = rx - s_kp[p * 3 + 0];
                float dy = ry - s_kp[p * 3 + 1];
                float dz = rz - s_kp[p * 3 + 2];
                float d  = sqrtf(fmaf(dx, dx, fmaf(dy, dy, dz * dz)));
                ib[p * 16] = __float2half_rn(fmaxf(1.0f - d, 0.0f));
            }
            ib[15 * 16] = __half(0.0f);
        }
        asm volatile("cp.async.wait_group 0;" ::: "memory");
        __syncthreads();

        // per-query mma aggregation: 2 queries per warp -> stage into s_A
        #pragma unroll
        for (int i = 0; i < 2; i++) {
            const int q  = wid * 2 + i;        // 0..15
            const int Lq = sbch * SB + q;      // 0..31 row in s_A chunks

            u32 a[4];
            ldmx4(a, sb + OFF_INFL + (u32)(q * 512 + aprow * 32) + abh);

            const u32 fbase = sb + OFF_SH + (u32)((q * 16 + krow) * 128);
            const u32 fswz  = (u32)((krow & 7) * 16);
            const int prow = lane >> 2;
            const int c4   = lane & 3;
            const u32 swzL = (u32)((Lq & 7) * 16);

            #pragma unroll
            for (int cc = 0; cc < 4; cc++) {
                u32 b[4];
                ldmx4t(b, fbase + (((u32)(cc * 32) + cbyte0) ^ fswz));
                float acc[2][4];
                #pragma unroll
                for (int h = 0; h < 2; h++)
                    #pragma unroll
                    for (int e = 0; e < 4; e++) acc[h][e] = 0.0f;
                mma_f16(acc[0], a, &b[0]);
                mma_f16(acc[1], a, &b[2]);

                #pragma unroll
                for (int h = 0; h < 2; h++) {
                    u32 lo = h2pk(acc[h][0], acc[h][1]);
                    u32 hi = h2pk(acc[h][2], acc[h][3]);
                    u32 x  = (u32)((2 * cc + h) * 16);
                    u32 off = (u32)(Lq * 128) + (x ^ swzL) + (u32)(c4 * 4);
                    *(u32*)(sm + OFF_A + prow * ACH + off) = lo;
                    if (prow != 7)
                        *(u32*)(sm + OFF_A + (prow + 8) * ACH + off) = hi;
                }
            }
        }
    }
    __syncthreads();   // s_A complete; f/infl dead -> B ring may start

    // =================== phase B: GEMM out[32x128] = s_A @ B^T ================
    const int wm = wid >> 2;        // 0..1 (M groups of 16)
    const int wn = wid & 3;         // 0..3 (N groups of 32)

    const int a_row  = wm * 16 + aprow;
    const u32 a_mask = (u32)((a_row & 7) * 16);
    const int b_row  = wn * 32 + (lane & 7) + ((lane >> 4) & 1) * 8;
    const int b_bh   = ((lane >> 3) & 1) * 16;
    const u32 b_mask = (u32)((b_row & 7) * 16);

    const int c0 = bid % NCHUNK;    // per-CTA chunk stagger

    float acc[4][4];
    #pragma unroll
    for (int ni = 0; ni < 4; ni++)
        #pragma unroll
        for (int e = 0; e < 4; e++) acc[ni][e] = 0.0f;

    auto issueB = [&](int i) {      // pipeline slot i -> chunk (c0+i)%15
        int cc = c0 + i; if (cc >= NCHUNK) cc -= NCHUNK;
        u32 dstb = sb + OFF_SH + (u32)(i % 3) * BTILE;
        #pragma unroll
        for (int j = 0; j < 4; j++) {
            int idx = tid + j * NT;               // 0..1023
            int row = idx >> 3, c16 = idx & 7;
            u32 dst = dstb + (u32)(row * 128 + ((c16 * 16) ^ ((row & 7) * 16)));
            cpa16(dst, g_B + (size_t)row * KTOT + cc * 64 + c16 * 8);
        }
        asm volatile("cp.async.commit_group;" ::: "memory");
    };

    issueB(0);
    issueB(1);

    for (int i = 0; i < NCHUNK; i++) {
        if (i < NCHUNK - 1) {
            asm volatile("cp.async.wait_group 1;" ::: "memory");
        } else {
            asm volatile("cp.async.wait_group 0;" ::: "memory");
        }
        __syncthreads();            // chunk i data published; chunk i-1 consumed
        if (i + 2 < NCHUNK) issueB(i + 2);   // overwrites buf (i-1)%3: safe

        int cc = c0 + i; if (cc >= NCHUNK) cc -= NCHUNK;
        const u32 aBase = sb + OFF_A + (u32)cc * ACH + (u32)(a_row * 128);
        const u32 bBase = sb + OFF_SH + (u32)(i % 3) * BTILE + (u32)(b_row * 128);

        #pragma unroll
        for (int ks = 0; ks < 4; ks++) {
            const u32 aOff = ((u32)(ks * 32) + abh) ^ a_mask;
            const u32 bOff = (u32)((ks * 32 + b_bh)) ^ b_mask;

            u32 b[8];
            #pragma unroll
            for (int nj = 0; nj < 2; nj++)
                ldmx4(&b[nj * 4], bBase + (u32)(nj * 16 * 128) + bOff);

            u32 a[4];
            ldmx4(a, aBase + aOff);
            #pragma unroll
            for (int ni = 0; ni < 4; ni++)
                mma_f16(acc[ni], a, &b[(ni >> 1) * 4 + (ni & 1) * 2]);
        }
    }

    // ---- epilogue ----
    {
        int row = m0 + wm * 16 + (lane >> 2);
        #pragma unroll
        for (int ni = 0; ni < 4; ni++) {
            int col = wn * 32 + ni * 8 + (lane & 3) * 2;
            *(float2*)(out + (size_t)row * COUT + col) =
                make_float2(acc[ni][0], acc[ni][1]);
            *(float2*)(out + (size_t)(row + 8) * COUT + col) =
                make_float2(acc[ni][2], acc[ni][3]);
        }
    }
}

// ================= launch =================
extern "C" void kernel_launch(void* const* d_in, const int* in_sizes, int n_in,
                              void* d_out, int out_size) {
    const float* query   = (const float*)d_in[0];
    const float* support = (const float*)d_in[1];
    const int*   nidx    = (const int*)d_in[2];
    const float* feats   = (const float*)d_in[3];
    const float* W       = (const float*)d_in[4];
    const float* kp      = (const float*)d_in[5];
    float* out = (float*)d_out;

    cudaFuncSetAttribute(kpconv_fused,
                         cudaFuncAttributeMaxDynamicSharedMemorySize, SMEM_TOT);
    kpconv_fused<<<NTOT / QB, NT, SMEM_TOT>>>(
        query, support, nidx, feats, kp, W, out);
}